// round 7
// baseline (speedup 1.0000x reference)
#include <cuda_runtime.h>
#include <cstdint>

#define BATCH   256
#define TSTEPS  1000
#define LIN     30
#define NCH     16
#define KW      7
#define LO      24
#define JDIM    384      // NCH*LO
#define NOUT    35
#define OPAD    36       // padded outputs
#define GR      12       // j-groups per output
#define JT      32       // j's per FC thread (GR*JT == JDIM)
#define NTHREADS 640     // 20 warps: B on 0-431, A on 448-639 (pair conv), C on 576-610
#define ATH0    448      // first A thread
#define NA      192      // A threads (each owns 2 positions)
#define CHUNK   50       // timesteps of x per smem chunk
#define NCHUNK  (TSTEPS / CHUNK)

typedef unsigned long long ull;

__device__ __forceinline__ uint32_t smem_u32(const void* p) {
    return (uint32_t)__cvta_generic_to_shared(p);
}
__device__ __forceinline__ void cp_async8(uint32_t dst, const void* src) {
    asm volatile("cp.async.ca.shared.global [%0], [%1], 8;" :: "r"(dst), "l"(src));
}
__device__ __forceinline__ void cp_commit() { asm volatile("cp.async.commit_group;"); }
__device__ __forceinline__ void cp_wait1()  { asm volatile("cp.async.wait_group 1;" ::: "memory"); }
__device__ __forceinline__ void cp_wait0()  { asm volatile("cp.async.wait_group 0;" ::: "memory"); }

__device__ __forceinline__ ull pk(float a, float b) {
    ull r; asm("mov.b64 %0, {%1,%2};" : "=l"(r) : "f"(a), "f"(b)); return r;
}
__device__ __forceinline__ void upk(ull v, float& a, float& b) {
    asm("mov.b64 {%0,%1}, %2;" : "=f"(a), "=f"(b) : "l"(v));
}
__device__ __forceinline__ ull f2mul(ull a, ull b) {
    ull d; asm("mul.rn.f32x2 %0, %1, %2;" : "=l"(d) : "l"(a), "l"(b)); return d;
}
__device__ __forceinline__ ull f2fma(ull a, ull b, ull c) {
    ull d; asm("fma.rn.f32x2 %0, %1, %2, %3;" : "=l"(d) : "l"(a), "l"(b), "l"(c)); return d;
}

// One pipelined iteration: C(t-2), B(t-1), A(t); single barrier at the end.
// Parities: A writes spk[pa]; B reads spk[pa^1], writes part[pa^1];
//           C reads part[pa]   (pa = t & 1).
#define STEP(PA, XROW, DOA, DOB, DOC)                                          \
  {                                                                            \
    const int pa_ = (PA);                                                      \
    if ((DOC) && cTh) {                                                        \
      float c2 = part[pa_][0][cIdx];                                           \
      _Pragma("unroll")                                                        \
      for (int rr = 1; rr < GR; ++rr) c2 += part[pa_][rr][cIdx];               \
      c2 = __fadd_rn(c2, bias2);                                               \
      float r2 = (mem2 > 1.0f) ? 1.0f : 0.0f;                                  \
      mem2 = __fsub_rn(__fadd_rn(__fmul_rn(0.9f, mem2), c2), r2);              \
      acc += (double)mem2;                                                     \
    }                                                                          \
    if ((DOB) && fcth) {                                                       \
      uint32_t sp = spkAddr + (uint32_t)((pa_ ^ 1) * (JDIM * 4));              \
      ull a0 = 0ull, a1 = 0ull;                                                \
      _Pragma("unroll")                                                        \
      for (int k = 0; k < JT / 2; k += 2) {                                    \
        ull s0, s1;                                                            \
        asm("ld.shared.v2.u64 {%0,%1}, [%2];"                                  \
            : "=l"(s0), "=l"(s1) : "r"(sp + (uint32_t)(k * 8)));               \
        a0 = f2fma(s0, w2[k],     a0);                                         \
        a1 = f2fma(s1, w2[k + 1], a1);                                         \
      }                                                                        \
      float x0_, x1_, y0_, y1_;                                                \
      upk(a0, x0_, x1_);                                                       \
      upk(a1, y0_, y1_);                                                       \
      part[pa_ ^ 1][r][o] = (x0_ + x1_) + (y0_ + y1_);                         \
    }                                                                          \
    if ((DOA) && aTh) {                                                        \
      const float2* xr2 = (const float2*)((XROW) + 2 * p);                     \
      float2 q0 = xr2[0], q1 = xr2[1], q2 = xr2[2], q3 = xr2[3];               \
      ull s2 = f2mul(pk(q0.x, q0.y), wc2[0]);                                  \
      s2 = f2fma(pk(q0.y, q1.x), wc2[1], s2);                                  \
      s2 = f2fma(pk(q1.x, q1.y), wc2[2], s2);                                  \
      s2 = f2fma(pk(q1.y, q2.x), wc2[3], s2);                                  \
      s2 = f2fma(pk(q2.x, q2.y), wc2[4], s2);                                  \
      s2 = f2fma(pk(q2.y, q3.x), wc2[5], s2);                                  \
      s2 = f2fma(pk(q3.x, q3.y), wc2[6], s2);                                  \
      float sa, sb;                                                            \
      upk(s2, sa, sb);                                                         \
      float c1a = __fadd_rn(sa, bc);                                           \
      float r1a = (m1a > 1.0f) ? 1.0f : 0.0f;                                  \
      m1a = __fsub_rn(__fadd_rn(__fmul_rn(0.9f, m1a), c1a), r1a);              \
      float spa = (m1a > 1.0f) ? 1.0f : 0.0f;                                  \
      float c1b = __fadd_rn(sb, bc);                                           \
      float r1b = (m1b > 1.0f) ? 1.0f : 0.0f;                                  \
      m1b = __fsub_rn(__fadd_rn(__fmul_rn(0.9f, m1b), c1b), r1b);              \
      float spb = (m1b > 1.0f) ? 1.0f : 0.0f;                                  \
      *(float2*)&spk[pa_][jA] = make_float2(spa, spb);                         \
    }                                                                          \
    __syncthreads();                                                           \
  }

__global__ __launch_bounds__(NTHREADS, 2)
void snn_kernel(const float* __restrict__ x,
                const float* __restrict__ conv_w,
                const float* __restrict__ conv_b,
                const float* __restrict__ fc_w,
                const float* __restrict__ fc_b,
                float* __restrict__ out)
{
    __shared__ __align__(16) float xs[2][CHUNK * LIN];   // 12 KB double-buffered x
    __shared__ __align__(16) float spk[2][JDIM];         // double-buffered spikes
    __shared__ float part[2][GR][40];                    // double-buffered FC partials

    const int b   = blockIdx.x;
    const int tid = threadIdx.x;

    // ---- Phase A state: threads 448-639, each owns positions (2p, 2p+1) of channel ch ----
    const bool aTh = (tid >= ATH0);
    const int  aidx = tid - ATH0;          // 0..191
    const int  ch   = aidx / (LO / 2);     // 0..15
    const int  p    = aidx % (LO / 2);     // 0..11  (pos = 2p)
    const int  jA   = ch * LO + 2 * p;
    ull   wc2[KW];
    float bc = 0.f, m1a = 0.f, m1b = 0.f;
    if (aTh) {
        #pragma unroll
        for (int k = 0; k < KW; ++k) {
            float w = conv_w[ch * KW + k];
            wc2[k] = pk(w, w);
        }
        bc = conv_b[ch];
    }

    // ---- Phase B state: threads 0-431 -> output o = tid%36, group r = tid/36 ----
    const bool fcth = (tid < GR * OPAD);
    const int  o    = tid % OPAD;
    const int  r    = tid / OPAD;
    ull w2[JT / 2];
    if (fcth) {
        #pragma unroll
        for (int k = 0; k < JT / 2; ++k) {
            float lo_ = 0.f, hi_ = 0.f;
            if (o < NOUT) {
                lo_ = fc_w[o * JDIM + r * JT + 2 * k];
                hi_ = fc_w[o * JDIM + r * JT + 2 * k + 1];
            }
            w2[k] = pk(lo_, hi_);
        }
    }
    const uint32_t spkAddr = smem_u32(&spk[0][r * JT]);

    // ---- Phase C state: threads 576..610 own output cIdx (ride on A warps 18-19) ----
    const bool cTh  = (tid >= 576) && (tid < 576 + NOUT);
    const int  cIdx = tid - 576;
    float  bias2 = 0.f, mem2 = 0.f;
    double acc   = 0.0;
    if (cTh) bias2 = fc_b[cIdx];

    const float* xb = x + (size_t)b * TSTEPS * LIN;

    // ---- prefetch chunk 0 (A threads only: 750 x 8B over 192 threads) ----
    if (aTh) {
        uint32_t sbase = smem_u32(&xs[0][0]);
        for (int i = aidx; i < CHUNK * LIN / 2; i += NA)
            cp_async8(sbase + i * 8, xb + i * 2);
    }
    cp_commit();

    for (int chunk = 0; chunk < NCHUNK; ++chunk) {
        const int buf = chunk & 1;
        if (chunk + 1 < NCHUNK) {
            if (aTh) {
                uint32_t sbase   = smem_u32(&xs[buf ^ 1][0]);
                const float* src = xb + (size_t)(chunk + 1) * CHUNK * LIN;
                for (int i = aidx; i < CHUNK * LIN / 2; i += NA)
                    cp_async8(sbase + i * 8, src + i * 2);
            }
            cp_commit();
            cp_wait1();
        } else {
            cp_wait0();
        }
        __syncthreads();

        const float* xrow = &xs[buf][0];
        if (chunk == 0) {
            // pipeline fill: B off at tc=0, C off at tc<2
            #pragma unroll 2
            for (int tc = 0; tc < CHUNK; ++tc)
                STEP(tc & 1, xrow + tc * LIN, true, tc >= 1, tc >= 2);
        } else {
            // steady state ((chunk*50 + tc) & 1 == tc & 1 since CHUNK is even)
            #pragma unroll 2
            for (int tc = 0; tc < CHUNK; ++tc)
                STEP(tc & 1, xrow + tc * LIN, true, true, true);
        }
    }

    // ---- pipeline drain: t=1000 (B(999), C(998)), t=1001 (C(999)) ----
    STEP(0, (const float*)nullptr, false, true, true);
    STEP(1, (const float*)nullptr, false, false, true);

    if (cTh)
        out[b * NOUT + cIdx] = (float)(acc * (1.0 / (double)TSTEPS));
}

extern "C" void kernel_launch(void* const* d_in, const int* in_sizes, int n_in,
                              void* d_out, int out_size)
{
    const float* x      = (const float*)d_in[0];
    const float* conv_w = (const float*)d_in[1];
    const float* conv_b = (const float*)d_in[2];
    const float* fc_w   = (const float*)d_in[3];
    const float* fc_b   = (const float*)d_in[4];
    snn_kernel<<<BATCH, NTHREADS>>>(x, conv_w, conv_b, fc_w, fc_b, (float*)d_out);
}